// round 1
// baseline (speedup 1.0000x reference)
#include <cuda_runtime.h>

// L2DistAttention on GB300 — round 0 baseline (fp32 everywhere).
// Pipeline:
//   k_detect      : classify neighbor_mask dtype (u8 / i32 / f32) -> g_maskmode
//   k_prenorm_proj: RMS prenorm + q/xi/xj projections
//   k_xe          : neighbor gather xe = xj[nbr] + xi
//   k_radial      : radial MLP (silu+LN, silu+LN) -> hdd
//   k_fold        : W3f[(r,d)|bias][o] = (rp_W3 reshaped + b3 row) @ Wkv_out
//   k_main        : kv2[e][o] = sum_{r,d} hdd[e,r]*xe[e,d]*W3f[(r,d)][o]
//                              + sum_d xe[e,d]*W3f[bias_d][o]   (the 8.7 GMAC GEMM)
//   k_att         : L2-distance attention over 16 neighbors, 4 heads
//   k_out         : out @ Wout

#define BN   512     // b*n
#define NE   8192    // b*n*k edges
#define DD   64      // d
#define HID  128
#define KVD  256
#define RH   64
#define KROWS 4160   // 64*64 + 64 bias rows

__device__ float g_q  [BN*HID];
__device__ float g_xi [BN*DD];
__device__ float g_xj [BN*DD];
__device__ float g_xe [NE*DD];
__device__ float g_hdd[NE*RH];
__device__ float g_W3f[KROWS*KVD];
__device__ float g_kv [NE*KVD];
__device__ float g_att[BN*HID];
__device__ int   g_maskmode;

// ---------------------------------------------------------------- mask dtype
__global__ void k_detect(const unsigned char* mb) {
    __shared__ int red[256];
    int t = threadIdx.x;
    int s = 0;
    for (int i = t; i < 8192; i += 256) s += mb[i];
    red[t] = s; __syncthreads();
    for (int o = 128; o; o >>= 1) { if (t < o) red[t] += red[t+o]; __syncthreads(); }
    if (t == 0) {
        int tot = red[0];
        // u8 0/1 bytes (~90% ones) -> ~7373 ; i32 (first 2048 ints) -> ~1843 ;
        // f32 (1.0f = ..,0x80,0x3F) -> ~352k
        g_maskmode = (tot > 100000) ? 2 : ((tot > 4000) ? 0 : 1);
    }
}

// ------------------------------------------------------- prenorm + projections
__global__ void k_prenorm_proj(const float* __restrict__ feat,
                               const float* __restrict__ gamma,
                               const float* __restrict__ Wq,
                               const float* __restrict__ Wxi,
                               const float* __restrict__ Wxj) {
    int node = blockIdx.x;
    __shared__ float xs[DD];
    __shared__ float red[DD];
    __shared__ float sinv;
    int t = threadIdx.x;  // 256
    if (t < 64) { float f = feat[node*64 + t]; red[t] = f*f; }
    __syncthreads();
    if (t < 32) {
        float v = red[t] + red[t+32];
        for (int o = 16; o; o >>= 1) v += __shfl_xor_sync(0xffffffffu, v, o);
        if (t == 0) {
            float rms = sqrtf(v) * 0.125f;             // * d^-0.5
            sinv = 1.0f / fmaxf(rms, 1e-12f);
        }
    }
    __syncthreads();
    if (t < 64) xs[t] = feat[node*64 + t] * sinv * gamma[t];
    __syncthreads();
    if (t < 128) {
        float acc = 0.f;
        #pragma unroll 16
        for (int d = 0; d < 64; d++) acc = fmaf(xs[d], Wq[d*128 + t], acc);
        g_q[node*128 + t] = acc;
    } else if (t < 192) {
        int c = t - 128; float acc = 0.f;
        #pragma unroll 16
        for (int d = 0; d < 64; d++) acc = fmaf(xs[d], Wxi[d*64 + c], acc);
        g_xi[node*64 + c] = acc;
    } else {
        int c = t - 192; float acc = 0.f;
        #pragma unroll 16
        for (int d = 0; d < 64; d++) acc = fmaf(xs[d], Wxj[d*64 + c], acc);
        g_xj[node*64 + c] = acc;
    }
}

// ---------------------------------------------------------------- edge gather
__global__ void k_xe(const int* __restrict__ nidx) {
    int i = blockIdx.x * 256 + threadIdx.x;    // < NE*DD
    int e = i >> 6, d = i & 63;
    int node = e >> 4;                          // b*256+n
    int b    = node >> 8;
    int nb   = nidx[e];                         // 0..255
    g_xe[i] = g_xj[(b*256 + nb)*64 + d] + g_xi[node*64 + d];
}

// ----------------------------------------------------------------- radial MLP
__global__ void k_radial(const float* __restrict__ rel,
                         const float* __restrict__ W1, const float* __restrict__ b1,
                         const float* __restrict__ g1,
                         const float* __restrict__ W2, const float* __restrict__ b2,
                         const float* __restrict__ g2) {
    __shared__ float sW2[RH*RH];
    __shared__ float sh[RH];
    __shared__ float red[RH];
    __shared__ float sbc[2];
    int t = threadIdx.x;  // 64
    for (int i = t; i < RH*RH; i += 64) sW2[i] = W2[i];
    float w1 = W1[t], bb1 = b1[t], gg1 = g1[t], bb2 = b2[t], gg2 = g2[t];
    __syncthreads();
    int e0 = blockIdx.x * 32;
    for (int i = 0; i < 32; i++) {
        int e = e0 + i;
        float s = rel[e];
        float a = fmaf(s, w1, bb1);
        float h = a / (1.0f + expf(-a));                 // silu
        // LN1
        red[t] = h; __syncthreads();
        for (int o = 32; o; o >>= 1) { if (t < o) red[t] += red[t+o]; __syncthreads(); }
        if (t == 0) sbc[0] = red[0] * (1.0f/64.0f);
        __syncthreads();
        float c1 = h - sbc[0];
        red[t] = c1*c1; __syncthreads();
        for (int o = 32; o; o >>= 1) { if (t < o) red[t] += red[t+o]; __syncthreads(); }
        if (t == 0) sbc[1] = rsqrtf(red[0] * (1.0f/64.0f) + 1e-5f);
        __syncthreads();
        sh[t] = c1 * sbc[1] * gg1;
        __syncthreads();
        // layer 2
        float acc = bb2;
        #pragma unroll 16
        for (int r = 0; r < 64; r++) acc = fmaf(sh[r], sW2[r*64 + t], acc);
        float h2 = acc / (1.0f + expf(-acc));
        // LN2
        red[t] = h2; __syncthreads();
        for (int o = 32; o; o >>= 1) { if (t < o) red[t] += red[t+o]; __syncthreads(); }
        if (t == 0) sbc[0] = red[0] * (1.0f/64.0f);
        __syncthreads();
        float c2 = h2 - sbc[0];
        red[t] = c2*c2; __syncthreads();
        for (int o = 32; o; o >>= 1) { if (t < o) red[t] += red[t+o]; __syncthreads(); }
        if (t == 0) sbc[1] = rsqrtf(red[0] * (1.0f/64.0f) + 1e-5f);
        __syncthreads();
        g_hdd[e*64 + t] = c2 * sbc[1] * gg2;
        __syncthreads();
    }
}

// ---------------- fold: W3f = [rp_W3 reshaped ; b3 row-block] @ Wkv_out
// A[kidx = r*64+d][o'] = rp_W3[r][o'*64+d]   (r<64)
// A[4096 + d][o']      = b3[o'*64+d]
__global__ void __launch_bounds__(256) k_fold(const float* __restrict__ W3,
                                              const float* __restrict__ b3,
                                              const float* __restrict__ Wkv) {
    __shared__ float As [64][64];   // [k=o'][m=d]
    __shared__ float Bsh[64][64];   // [k=o'][n]
    int tid = threadIdx.x, tx = tid & 15, ty = tid >> 4;
    int mb = blockIdx.x;            // 0..64 : r (or bias block 64)
    int ob = blockIdx.y * 64;
    float acc[4][4] = {};
    for (int kc = 0; kc < 256; kc += 64) {
        __syncthreads();
        #pragma unroll
        for (int q = 0; q < 4; q++) {
            int f4 = tid + 256*q; int kl = f4 >> 4; int d4 = (f4 & 15) * 4;
            float4 av;
            if (mb < 64) av = *(const float4*)&W3[(size_t)mb*16384 + (size_t)(kc+kl)*64 + d4];
            else         av = *(const float4*)&b3[(size_t)(kc+kl)*64 + d4];
            *(float4*)&As[kl][d4] = av;
            *(float4*)&Bsh[kl][d4] = *(const float4*)&Wkv[(size_t)(kc+kl)*256 + ob + d4];
        }
        __syncthreads();
        #pragma unroll 16
        for (int k = 0; k < 64; k++) {
            float4 a4 = *(const float4*)&As[k][ty*4];
            float4 b4 = *(const float4*)&Bsh[k][tx*4];
            acc[0][0]=fmaf(a4.x,b4.x,acc[0][0]); acc[0][1]=fmaf(a4.x,b4.y,acc[0][1]);
            acc[0][2]=fmaf(a4.x,b4.z,acc[0][2]); acc[0][3]=fmaf(a4.x,b4.w,acc[0][3]);
            acc[1][0]=fmaf(a4.y,b4.x,acc[1][0]); acc[1][1]=fmaf(a4.y,b4.y,acc[1][1]);
            acc[1][2]=fmaf(a4.y,b4.z,acc[1][2]); acc[1][3]=fmaf(a4.y,b4.w,acc[1][3]);
            acc[2][0]=fmaf(a4.z,b4.x,acc[2][0]); acc[2][1]=fmaf(a4.z,b4.y,acc[2][1]);
            acc[2][2]=fmaf(a4.z,b4.z,acc[2][2]); acc[2][3]=fmaf(a4.z,b4.w,acc[2][3]);
            acc[3][0]=fmaf(a4.w,b4.x,acc[3][0]); acc[3][1]=fmaf(a4.w,b4.y,acc[3][1]);
            acc[3][2]=fmaf(a4.w,b4.z,acc[3][2]); acc[3][3]=fmaf(a4.w,b4.w,acc[3][3]);
        }
    }
    #pragma unroll
    for (int i = 0; i < 4; i++) {
        *(float4*)&g_W3f[(size_t)(mb*64 + ty*4 + i)*256 + ob + tx*4] =
            make_float4(acc[i][0], acc[i][1], acc[i][2], acc[i][3]);
    }
}

// ---------------- main z-GEMM: kv2 = z @ W3f  (z formed on the fly)
__global__ void __launch_bounds__(256) k_main() {
    __shared__ float xeT[64][64];   // [d][e_local]
    __shared__ float hT [64][64];   // [r][e_local]
    __shared__ float Bs [64][64];   // [d][o_local] for current r
    int tid = threadIdx.x;
    int tx = tid & 15, ty = tid >> 4;
    int eb = blockIdx.x * 64;       // edge base
    int ob = blockIdx.y * 64;       // out-col base
    for (int i = tid; i < 4096; i += 256) {
        int e = i >> 6, d = i & 63;
        xeT[d][e] = g_xe [(size_t)(eb+e)*64 + d];
        hT [d][e] = g_hdd[(size_t)(eb+e)*64 + d];
    }
    float4 nb[4];
    #pragma unroll
    for (int q = 0; q < 4; q++) {                    // prefetch r=0 slice
        int f4 = tid + 256*q; int d = f4 >> 4; int oc = (f4 & 15) * 4;
        nb[q] = *(const float4*)&g_W3f[(size_t)d*256 + ob + oc];
    }
    float acc[4][4];
    #pragma unroll
    for (int i = 0; i < 4; i++)
        #pragma unroll
        for (int j = 0; j < 4; j++) acc[i][j] = 0.f;
    __syncthreads();
    for (int r = 0; r < 65; r++) {                   // r=64 -> bias rows, ah=1
        #pragma unroll
        for (int q = 0; q < 4; q++) {
            int f4 = tid + 256*q; int d = f4 >> 4; int oc = (f4 & 15) * 4;
            *(float4*)&Bs[d][oc] = nb[q];
        }
        __syncthreads();
        if (r < 64) {                                // prefetch next slice
            int base = (r < 63) ? (r+1)*64 : 4096;
            #pragma unroll
            for (int q = 0; q < 4; q++) {
                int f4 = tid + 256*q; int d = f4 >> 4; int oc = (f4 & 15) * 4;
                nb[q] = *(const float4*)&g_W3f[(size_t)(base+d)*256 + ob + oc];
            }
        }
        float4 ah;
        if (r < 64) ah = *(const float4*)&hT[r][ty*4];
        else        ah = make_float4(1.f, 1.f, 1.f, 1.f);
        #pragma unroll 16
        for (int d = 0; d < 64; d++) {
            float4 xv = *(const float4*)&xeT[d][ty*4];
            float4 bv = *(const float4*)&Bs[d][tx*4];
            float a0 = ah.x*xv.x, a1 = ah.y*xv.y, a2 = ah.z*xv.z, a3 = ah.w*xv.w;
            acc[0][0]=fmaf(a0,bv.x,acc[0][0]); acc[0][1]=fmaf(a0,bv.y,acc[0][1]);
            acc[0][2]=fmaf(a0,bv.z,acc[0][2]); acc[0][3]=fmaf(a0,bv.w,acc[0][3]);
            acc[1][0]=fmaf(a1,bv.x,acc[1][0]); acc[1][1]=fmaf(a1,bv.y,acc[1][1]);
            acc[1][2]=fmaf(a1,bv.z,acc[1][2]); acc[1][3]=fmaf(a1,bv.w,acc[1][3]);
            acc[2][0]=fmaf(a2,bv.x,acc[2][0]); acc[2][1]=fmaf(a2,bv.y,acc[2][1]);
            acc[2][2]=fmaf(a2,bv.z,acc[2][2]); acc[2][3]=fmaf(a2,bv.w,acc[2][3]);
            acc[3][0]=fmaf(a3,bv.x,acc[3][0]); acc[3][1]=fmaf(a3,bv.y,acc[3][1]);
            acc[3][2]=fmaf(a3,bv.z,acc[3][2]); acc[3][3]=fmaf(a3,bv.w,acc[3][3]);
        }
        __syncthreads();
    }
    #pragma unroll
    for (int i = 0; i < 4; i++) {
        *(float4*)&g_kv[(size_t)(eb + ty*4 + i)*256 + ob + tx*4] =
            make_float4(acc[i][0], acc[i][1], acc[i][2], acc[i][3]);
    }
}

// ----------------------------------------------------------------- attention
__global__ void k_att(const void* __restrict__ maskbuf) {
    int node = blockIdx.x;
    int h = threadIdx.x >> 5, l = threadIdx.x & 31;
    float qv = g_q[node*128 + h*32 + l];
    int mode = g_maskmode;
    int ebase = node * 16;
    float sim[16];
    #pragma unroll
    for (int j = 0; j < 16; j++) {
        int e = ebase + j;
        float kvv = g_kv[(size_t)e*256 + h*32 + l];
        float df = qv - kvv + 1e-6f;
        float s = df * df;
        #pragma unroll
        for (int o = 16; o; o >>= 1) s += __shfl_xor_sync(0xffffffffu, s, o);
        bool m;
        if      (mode == 0) m = ((const unsigned char*)maskbuf)[e] != 0;
        else if (mode == 1) m = ((const int*)maskbuf)[e] != 0;
        else                m = ((const float*)maskbuf)[e] != 0.0f;
        sim[j] = m ? (-sqrtf(s) * 0.17677669529663687f)   // * dh^-0.5
                   : -3.4028234663852886e38f;
    }
    float mx = sim[0];
    #pragma unroll
    for (int j = 1; j < 16; j++) mx = fmaxf(mx, sim[j]);
    float w[16], Z = 0.f;
    #pragma unroll
    for (int j = 0; j < 16; j++) { w[j] = expf(sim[j] - mx); Z += w[j]; }
    float inv = 1.0f / Z;
    float out = 0.f;
    #pragma unroll
    for (int j = 0; j < 16; j++)
        out = fmaf(w[j] * inv, g_kv[(size_t)(ebase+j)*256 + 128 + h*32 + l], out);
    g_att[node*128 + h*32 + l] = out;
}

// ---------------------------------------------------------------- out proj
__global__ void k_out(const float* __restrict__ Wout, float* __restrict__ out) {
    __shared__ float a[HID];
    int node = blockIdx.x, t = threadIdx.x;  // 64
    a[t]      = g_att[node*128 + t];
    a[t + 64] = g_att[node*128 + t + 64];
    __syncthreads();
    float acc = 0.f;
    #pragma unroll 16
    for (int i = 0; i < 128; i++) acc = fmaf(a[i], Wout[i*64 + t], acc);
    out[node*64 + t] = acc;
}

// -------------------------------------------------------------------- launch
extern "C" void kernel_launch(void* const* d_in, const int* in_sizes, int n_in,
                              void* d_out, int out_size) {
    const float* feat  = (const float*)d_in[0];
    const int*   nidx  = (const int*)  d_in[1];
    const void*  mask  =               d_in[2];
    const float* rel   = (const float*)d_in[3];
    const float* gamma = (const float*)d_in[4];
    const float* Wq    = (const float*)d_in[5];
    const float* Wxi   = (const float*)d_in[6];
    const float* Wxj   = (const float*)d_in[7];
    const float* W1    = (const float*)d_in[8];
    const float* b1    = (const float*)d_in[9];
    const float* g1    = (const float*)d_in[10];
    const float* W2    = (const float*)d_in[11];
    const float* b2    = (const float*)d_in[12];
    const float* g2    = (const float*)d_in[13];
    const float* W3    = (const float*)d_in[14];
    const float* b3    = (const float*)d_in[15];
    const float* Wkv   = (const float*)d_in[16];
    const float* Wout  = (const float*)d_in[17];

    k_detect<<<1, 256>>>((const unsigned char*)mask);
    k_prenorm_proj<<<BN, 256>>>(feat, gamma, Wq, Wxi, Wxj);
    k_xe<<<NE*DD/256, 256>>>(nidx);
    k_radial<<<NE/32, 64>>>(rel, W1, b1, g1, W2, b2, g2);
    k_fold<<<dim3(65, 4), 256>>>(W3, b3, Wkv);
    k_main<<<dim3(NE/64, 4), 256>>>();
    k_att<<<BN, 128>>>(mask);
    k_out<<<BN, 64>>>(Wout, (float*)d_out);
}

// round 3
// speedup vs baseline: 2.5225x; 2.5225x over previous
#include <cuda_runtime.h>
#include <cuda_bf16.h>
#include <cstdint>

// L2DistAttention — round 2 (resubmit of round-1 kernel; prior bench hit
// GPUAcquisitionTimeout): bf16 tensor-core z-GEMM (3-split) + warp-per-edge
// radial MLP.

#define BN   512
#define NE   8192
#define DD   64
#define HID  128
#define KVD  256
#define RH   64
#define KROWS 4160

__device__ float g_q  [BN*HID];
__device__ float g_xi [BN*DD];
__device__ float g_xj [BN*DD];
__device__ float g_xe [NE*DD];
__device__ float g_hdd[NE*RH];
__device__ __nv_bfloat16 g_Whi[KROWS*KVD];
__device__ __nv_bfloat16 g_Wlo[KROWS*KVD];
__device__ float g_kv [NE*KVD];
__device__ float g_att[BN*HID];
__device__ int   g_maskmode;

// ------------------------------------------------------------------ helpers
__device__ __forceinline__ uint32_t smem_u32(const void* p) {
    return (uint32_t)__cvta_generic_to_shared(p);
}
__device__ __forceinline__ void ldsm4(uint32_t& r0, uint32_t& r1, uint32_t& r2, uint32_t& r3,
                                      uint32_t addr) {
    asm volatile("ldmatrix.sync.aligned.m8n8.x4.shared.b16 {%0,%1,%2,%3}, [%4];"
                 : "=r"(r0), "=r"(r1), "=r"(r2), "=r"(r3) : "r"(addr));
}
__device__ __forceinline__ void ldsm4t(uint32_t& r0, uint32_t& r1, uint32_t& r2, uint32_t& r3,
                                       uint32_t addr) {
    asm volatile("ldmatrix.sync.aligned.m8n8.x4.trans.shared.b16 {%0,%1,%2,%3}, [%4];"
                 : "=r"(r0), "=r"(r1), "=r"(r2), "=r"(r3) : "r"(addr));
}
__device__ __forceinline__ void mma16816(float* c, const uint32_t* a, const uint32_t* b) {
    asm volatile("mma.sync.aligned.m16n8k16.row.col.f32.bf16.bf16.f32 "
                 "{%0,%1,%2,%3},{%4,%5,%6,%7},{%8,%9},{%0,%1,%2,%3};"
                 : "+f"(c[0]), "+f"(c[1]), "+f"(c[2]), "+f"(c[3])
                 : "r"(a[0]), "r"(a[1]), "r"(a[2]), "r"(a[3]), "r"(b[0]), "r"(b[1]));
}
__device__ __forceinline__ uint32_t packbf(__nv_bfloat16 a, __nv_bfloat16 b) {
    return (uint32_t)__bfloat16_as_ushort(a) | ((uint32_t)__bfloat16_as_ushort(b) << 16);
}

// ---------------------------------------------------------------- mask dtype
__global__ void k_detect(const unsigned char* mb) {
    __shared__ int red[256];
    int t = threadIdx.x;
    int s = 0;
    for (int i = t; i < 8192; i += 256) s += mb[i];
    red[t] = s; __syncthreads();
    for (int o = 128; o; o >>= 1) { if (t < o) red[t] += red[t+o]; __syncthreads(); }
    if (t == 0) {
        int tot = red[0];
        g_maskmode = (tot > 100000) ? 2 : ((tot > 4000) ? 0 : 1);
    }
}

// ------------------------------------------------------- prenorm + projections
__global__ void k_prenorm_proj(const float* __restrict__ feat,
                               const float* __restrict__ gamma,
                               const float* __restrict__ Wq,
                               const float* __restrict__ Wxi,
                               const float* __restrict__ Wxj) {
    int node = blockIdx.x;
    __shared__ float xs[DD];
    __shared__ float red[DD];
    __shared__ float sinv;
    int t = threadIdx.x;  // 256
    if (t < 64) { float f = feat[node*64 + t]; red[t] = f*f; }
    __syncthreads();
    if (t < 32) {
        float v = red[t] + red[t+32];
        for (int o = 16; o; o >>= 1) v += __shfl_xor_sync(0xffffffffu, v, o);
        if (t == 0) {
            float rms = sqrtf(v) * 0.125f;
            sinv = 1.0f / fmaxf(rms, 1e-12f);
        }
    }
    __syncthreads();
    if (t < 64) xs[t] = feat[node*64 + t] * sinv * gamma[t];
    __syncthreads();
    if (t < 128) {
        float acc = 0.f;
        #pragma unroll 16
        for (int d = 0; d < 64; d++) acc = fmaf(xs[d], Wq[d*128 + t], acc);
        g_q[node*128 + t] = acc;
    } else if (t < 192) {
        int c = t - 128; float acc = 0.f;
        #pragma unroll 16
        for (int d = 0; d < 64; d++) acc = fmaf(xs[d], Wxi[d*64 + c], acc);
        g_xi[node*64 + c] = acc;
    } else {
        int c = t - 192; float acc = 0.f;
        #pragma unroll 16
        for (int d = 0; d < 64; d++) acc = fmaf(xs[d], Wxj[d*64 + c], acc);
        g_xj[node*64 + c] = acc;
    }
}

// ---------------------------------------------------------------- edge gather
__global__ void k_xe(const int* __restrict__ nidx) {
    int i = blockIdx.x * 256 + threadIdx.x;
    int e = i >> 6, d = i & 63;
    int node = e >> 4;
    int b    = node >> 8;
    int nb   = nidx[e];
    g_xe[i] = g_xj[(b*256 + nb)*64 + d] + g_xi[node*64 + d];
}

// ------------------------------------------------ radial MLP: warp per edge
__global__ void __launch_bounds__(256) k_radial(
        const float* __restrict__ rel,
        const float* __restrict__ W1, const float* __restrict__ b1,
        const float* __restrict__ g1,
        const float* __restrict__ W2, const float* __restrict__ b2,
        const float* __restrict__ g2) {
    __shared__ float sW2[RH*RH];   // 16KB
    int tid = threadIdx.x, lane = tid & 31, w = tid >> 5;
    for (int i = tid; i < RH*RH; i += 256) sW2[i] = W2[i];
    __syncthreads();
    int e = blockIdx.x * 8 + w;
    int c0 = lane * 2, c1 = c0 + 1;
    float s = rel[e];
    // layer 1 + silu
    float a0 = fmaf(s, W1[c0], b1[c0]);
    float a1 = fmaf(s, W1[c1], b1[c1]);
    float h0 = a0 / (1.0f + expf(-a0));
    float h1 = a1 / (1.0f + expf(-a1));
    // LN1 (warp-wide over 64 values)
    float sum = h0 + h1;
    #pragma unroll
    for (int o = 16; o; o >>= 1) sum += __shfl_xor_sync(0xffffffffu, sum, o);
    float mean = sum * (1.0f/64.0f);
    float d0 = h0 - mean, d1 = h1 - mean;
    float v = d0*d0 + d1*d1;
    #pragma unroll
    for (int o = 16; o; o >>= 1) v += __shfl_xor_sync(0xffffffffu, v, o);
    float rstd = rsqrtf(v * (1.0f/64.0f) + 1e-5f);
    float y0 = d0 * rstd * g1[c0];
    float y1 = d1 * rstd * g1[c1];
    // layer 2 matvec
    float o0 = b2[c0], o1 = b2[c1];
    #pragma unroll 8
    for (int r2 = 0; r2 < 32; r2++) {
        float yr0 = __shfl_sync(0xffffffffu, y0, r2);
        float yr1 = __shfl_sync(0xffffffffu, y1, r2);
        float2 w0 = *(const float2*)&sW2[(2*r2  )*64 + c0];
        float2 w1 = *(const float2*)&sW2[(2*r2+1)*64 + c0];
        o0 = fmaf(yr0, w0.x, fmaf(yr1, w1.x, o0));
        o1 = fmaf(yr0, w0.y, fmaf(yr1, w1.y, o1));
    }
    float h20 = o0 / (1.0f + expf(-o0));
    float h21 = o1 / (1.0f + expf(-o1));
    // LN2
    sum = h20 + h21;
    #pragma unroll
    for (int o = 16; o; o >>= 1) sum += __shfl_xor_sync(0xffffffffu, sum, o);
    mean = sum * (1.0f/64.0f);
    d0 = h20 - mean; d1 = h21 - mean;
    v = d0*d0 + d1*d1;
    #pragma unroll
    for (int o = 16; o; o >>= 1) v += __shfl_xor_sync(0xffffffffu, v, o);
    rstd = rsqrtf(v * (1.0f/64.0f) + 1e-5f);
    float2 outv = make_float2(d0 * rstd * g2[c0], d1 * rstd * g2[c1]);
    *(float2*)&g_hdd[e*64 + c0] = outv;
}

// ---------------- fold: W3f = [rp_W3 reshaped ; b3 row-block] @ Wkv_out -> bf16 hi/lo
__global__ void __launch_bounds__(256) k_fold(const float* __restrict__ W3,
                                              const float* __restrict__ b3,
                                              const float* __restrict__ Wkv) {
    __shared__ float As [64][64];
    __shared__ float Bsh[64][64];
    int tid = threadIdx.x, tx = tid & 15, ty = tid >> 4;
    int mb = blockIdx.x;            // 0..64 (64 = bias block)
    int ob = blockIdx.y * 64;
    float acc[4][4] = {};
    for (int kc = 0; kc < 256; kc += 64) {
        __syncthreads();
        #pragma unroll
        for (int q = 0; q < 4; q++) {
            int f4 = tid + 256*q; int kl = f4 >> 4; int d4 = (f4 & 15) * 4;
            float4 av;
            if (mb < 64) av = *(const float4*)&W3[(size_t)mb*16384 + (size_t)(kc+kl)*64 + d4];
            else         av = *(const float4*)&b3[(size_t)(kc+kl)*64 + d4];
            *(float4*)&As[kl][d4] = av;
            *(float4*)&Bsh[kl][d4] = *(const float4*)&Wkv[(size_t)(kc+kl)*256 + ob + d4];
        }
        __syncthreads();
        #pragma unroll 16
        for (int k = 0; k < 64; k++) {
            float4 a4 = *(const float4*)&As[k][ty*4];
            float4 b4 = *(const float4*)&Bsh[k][tx*4];
            acc[0][0]=fmaf(a4.x,b4.x,acc[0][0]); acc[0][1]=fmaf(a4.x,b4.y,acc[0][1]);
            acc[0][2]=fmaf(a4.x,b4.z,acc[0][2]); acc[0][3]=fmaf(a4.x,b4.w,acc[0][3]);
            acc[1][0]=fmaf(a4.y,b4.x,acc[1][0]); acc[1][1]=fmaf(a4.y,b4.y,acc[1][1]);
            acc[1][2]=fmaf(a4.y,b4.z,acc[1][2]); acc[1][3]=fmaf(a4.y,b4.w,acc[1][3]);
            acc[2][0]=fmaf(a4.z,b4.x,acc[2][0]); acc[2][1]=fmaf(a4.z,b4.y,acc[2][1]);
            acc[2][2]=fmaf(a4.z,b4.z,acc[2][2]); acc[2][3]=fmaf(a4.z,b4.w,acc[2][3]);
            acc[3][0]=fmaf(a4.w,b4.x,acc[3][0]); acc[3][1]=fmaf(a4.w,b4.y,acc[3][1]);
            acc[3][2]=fmaf(a4.w,b4.z,acc[3][2]); acc[3][3]=fmaf(a4.w,b4.w,acc[3][3]);
        }
    }
    #pragma unroll
    for (int i = 0; i < 4; i++) {
        size_t row = (size_t)(mb*64 + ty*4 + i);
        __nv_bfloat16 h[4], l[4];
        #pragma unroll
        for (int j = 0; j < 4; j++) {
            h[j] = __float2bfloat16_rn(acc[i][j]);
            l[j] = __float2bfloat16_rn(acc[i][j] - __bfloat162float(h[j]));
        }
        uint32_t* ph = (uint32_t*)&g_Whi[row*256 + ob + tx*4];
        uint32_t* pl = (uint32_t*)&g_Wlo[row*256 + ob + tx*4];
        ph[0] = packbf(h[0], h[1]); ph[1] = packbf(h[2], h[3]);
        pl[0] = packbf(l[0], l[1]); pl[1] = packbf(l[2], l[3]);
    }
}

// ---------------- main z-GEMM on tensor cores: kv = z @ W3f, z split to bf16 hi/lo
// BM=128, BN=128, chunk K=64 (one r per chunk; chunk 64 = bias rows, h=1)
__global__ void __launch_bounds__(256) k_main() {
    extern __shared__ char sm[];
    float* s_hT = (float*)sm;                 // [64 r][128 m]  32KB
    char*  sA   = sm + 32768;                 // A_hi 16KB | A_lo 16KB
    char*  sB   = sm + 65536;                 // 2 stages x (B_hi 16KB | B_lo 16KB)

    int tid  = threadIdx.x;
    int lane = tid & 31, warp = tid >> 5;
    int wm = warp & 3, wn = warp >> 2;        // 4 x 2 warp grid
    int eb = blockIdx.x * 128, ob = blockIdx.y * 128;

    // ---- async B-tile copy (hi+lo, 32KB) for chunk -> stage
    auto cpB = [&](int stage, int chunk) {
        char* st = sB + stage * 32768;
        #pragma unroll
        for (int i = 0; i < 8; i++) {
            int f = i * 256 + tid;            // 0..2047 granules
            int tile = f >> 10;               // 0=hi 1=lo
            int k    = (f >> 4) & 63;
            int gn   = f & 15;
            const __nv_bfloat16* src =
                (tile ? g_Wlo : g_Whi) + (size_t)(chunk*64 + k)*256 + ob + gn*8;
            uint32_t dst = smem_u32(st + tile*16384 + k*256 + ((gn ^ (k & 7)) * 16));
            asm volatile("cp.async.cg.shared.global [%0], [%1], 16;" :: "r"(dst), "l"(src));
        }
        asm volatile("cp.async.commit_group;");
    };

    cpB(0, 0);

    // xe row slice in registers: thread t -> row zm, cols zd..zd+31
    int zm = tid >> 1, zd = (tid & 1) * 32;
    float xr[32];
    #pragma unroll
    for (int j = 0; j < 32; j += 4)
        *(float4*)&xr[j] = *(const float4*)&g_xe[(size_t)(eb + zm)*64 + zd + j];

    // hdd tile transposed into smem
    for (int idx = tid; idx < 8192; idx += 256) {
        int rr = idx >> 7, m = idx & 127;
        s_hT[idx] = g_hdd[(size_t)(eb + m)*64 + rr];
    }

    float acc[2][8][4];
    #pragma unroll
    for (int a = 0; a < 2; a++)
        #pragma unroll
        for (int b = 0; b < 8; b++)
            #pragma unroll
            for (int c = 0; c < 4; c++) acc[a][b][c] = 0.f;

    uint32_t aAhi = smem_u32(sA);
    uint32_t aAlo = aAhi + 16384;
    uint32_t rowB = zm * 128;
    int      swm  = zm & 7;

    for (int r = 0; r < 65; ++r) {
        asm volatile("cp.async.wait_group 0;");
        __syncthreads();                       // B[r] visible; previous mma done
        if (r + 1 < 65) cpB((r + 1) & 1, r + 1);

        // z-compute: z = h * xe, split to bf16 hi/lo tiles
        float h = (r < 64) ? s_hT[r*128 + zm] : 1.0f;
        #pragma unroll
        for (int j = 0; j < 32; j += 2) {
            float z0 = h * xr[j], z1 = h * xr[j+1];
            __nv_bfloat16 h0 = __float2bfloat16_rn(z0);
            __nv_bfloat16 h1 = __float2bfloat16_rn(z1);
            __nv_bfloat16 l0 = __float2bfloat16_rn(z0 - __bfloat162float(h0));
            __nv_bfloat16 l1 = __float2bfloat16_rn(z1 - __bfloat162float(h1));
            int d = zd + j;
            uint32_t off = rowB + (((d >> 3) ^ swm) << 4) + ((d & 7) * 2);
            *(uint32_t*)(sA + off)         = packbf(h0, h1);
            *(uint32_t*)(sA + 16384 + off) = packbf(l0, l1);
        }
        __syncthreads();                       // A tiles ready

        // mma over 4 k-steps
        char* st = sB + (r & 1) * 32768;
        uint32_t aBhi = smem_u32(st);
        uint32_t aBlo = aBhi + 16384;
        #pragma unroll
        for (int ks = 0; ks < 4; ++ks) {
            uint32_t ahi[2][4], alo[2][4];
            #pragma unroll
            for (int mt = 0; mt < 2; ++mt) {
                int rrow = wm*32 + mt*16 + (lane & 7) + ((lane >> 3) & 1) * 8;
                int g    = ks*2 + ((lane >> 4) & 1);
                uint32_t off = rrow*128 + ((g ^ (rrow & 7)) << 4);
                ldsm4(ahi[mt][0], ahi[mt][1], ahi[mt][2], ahi[mt][3], aAhi + off);
                ldsm4(alo[mt][0], alo[mt][1], alo[mt][2], alo[mt][3], aAlo + off);
            }
            #pragma unroll
            for (int p = 0; p < 4; ++p) {
                int krow = ks*16 + (lane & 7) + ((lane >> 3) & 1) * 8;
                int ncol = wn*64 + p*16 + ((lane >> 4) & 1) * 8;
                uint32_t off = krow*256 + ((((ncol >> 3) ^ (krow & 7))) << 4);
                uint32_t bhi[4], blo[4];
                ldsm4t(bhi[0], bhi[1], bhi[2], bhi[3], aBhi + off);
                ldsm4t(blo[0], blo[1], blo[2], blo[3], aBlo + off);
                #pragma unroll
                for (int mt = 0; mt < 2; ++mt) {
                    mma16816(acc[mt][2*p],   ahi[mt], bhi);
                    mma16816(acc[mt][2*p],   alo[mt], bhi);
                    mma16816(acc[mt][2*p],   ahi[mt], blo);
                    mma16816(acc[mt][2*p+1], ahi[mt], bhi + 2);
                    mma16816(acc[mt][2*p+1], alo[mt], bhi + 2);
                    mma16816(acc[mt][2*p+1], ahi[mt], blo + 2);
                }
            }
        }
    }

    // epilogue: write fp32 kv
    int gq = lane >> 2, t4 = lane & 3;
    #pragma unroll
    for (int mt = 0; mt < 2; ++mt) {
        #pragma unroll
        for (int ng = 0; ng < 8; ++ng) {
            int row = eb + wm*32 + mt*16 + gq;
            int col = ob + wn*64 + ng*8 + t4*2;
            *(float2*)&g_kv[(size_t)row*256 + col]       =
                make_float2(acc[mt][ng][0], acc[mt][ng][1]);
            *(float2*)&g_kv[(size_t)(row + 8)*256 + col] =
                make_float2(acc[mt][ng][2], acc[mt][ng][3]);
        }
    }
}

// ----------------------------------------------------------------- attention
__global__ void k_att(const void* __restrict__ maskbuf) {
    int node = blockIdx.x;
    int h = threadIdx.x >> 5, l = threadIdx.x & 31;
    float qv = g_q[node*128 + h*32 + l];
    int mode = g_maskmode;
    int ebase = node * 16;
    float sim[16];
    #pragma unroll
    for (int j = 0; j < 16; j++) {
        int e = ebase + j;
        float kvv = g_kv[(size_t)e*256 + h*32 + l];
        float df = qv - kvv + 1e-6f;
        float s = df * df;
        #pragma unroll
        for (int o = 16; o; o >>= 1) s += __shfl_xor_sync(0xffffffffu, s, o);
        bool m;
        if      (mode == 0) m = ((const unsigned char*)maskbuf)[e] != 0;
        else if (mode == 1) m = ((const int*)maskbuf)[e] != 0;
        else                m = ((const float*)maskbuf)[e] != 0.0f;
        sim[j] = m ? (-sqrtf(s) * 0.17677669529663687f)
                   : -3.4028234663852886e38f;
    }
    float mx = sim[0];
    #pragma unroll
    for (int j = 1; j < 16; j++) mx = fmaxf(mx, sim[j]);
    float w[16], Z = 0.f;
    #pragma unroll
    for (int j = 0; j < 16; j++) { w[j] = expf(sim[j] - mx); Z += w[j]; }
    float inv = 1.0f / Z;
    float out = 0.f;
    #pragma unroll
    for (int j = 0; j < 16; j++)
        out = fmaf(w[j] * inv, g_kv[(size_t)(ebase+j)*256 + 128 + h*32 + l], out);
    g_att[node*128 + h*32 + l] = out;
}

// ---------------------------------------------------------------- out proj
__global__ void k_out(const float* __restrict__ Wout, float* __restrict__ out) {
    __shared__ float a[HID];
    int node = blockIdx.x, t = threadIdx.x;  // 64
    a[t]      = g_att[node*128 + t];
    a[t + 64] = g_att[node*128 + t + 64];
    __syncthreads();
    float acc = 0.f;
    #pragma unroll 16
    for (int i = 0; i < 128; i++) acc = fmaf(a[i], Wout[i*64 + t], acc);
    out[node*64 + t] = acc;
}

// -------------------------------------------------------------------- launch
extern "C" void kernel_launch(void* const* d_in, const int* in_sizes, int n_in,
                              void* d_out, int out_size) {
    const float* feat  = (const float*)d_in[0];
    const int*   nidx  = (const int*)  d_in[1];
    const void*  mask  =               d_in[2];
    const float* rel   = (const float*)d_in[3];
    const float* gamma = (const float*)d_in[4];
    const float* Wq    = (const float*)d_in[5];
    const float* Wxi   = (const float*)d_in[6];
    const float* Wxj   = (const float*)d_in[7];
    const float* W1    = (const float*)d_in[8];
    const float* b1    = (const float*)d_in[9];
    const float* g1    = (const float*)d_in[10];
    const float* W2    = (const float*)d_in[11];
    const float* b2    = (const float*)d_in[12];
    const float* g2    = (const float*)d_in[13];
    const float* W3    = (const float*)d_in[14];
    const float* b3    = (const float*)d_in[15];
    const float* Wkv   = (const float*)d_in[16];
    const float* Wout  = (const float*)d_in[17];

    cudaFuncSetAttribute(k_main, cudaFuncAttributeMaxDynamicSharedMemorySize, 131072);

    k_detect<<<1, 256>>>((const unsigned char*)mask);
    k_prenorm_proj<<<BN, 256>>>(feat, gamma, Wq, Wxi, Wxj);
    k_xe<<<NE*DD/256, 256>>>(nidx);
    k_radial<<<NE/8, 256>>>(rel, W1, b1, g1, W2, b2, g2);
    k_fold<<<dim3(65, 4), 256>>>(W3, b3, Wkv);
    k_main<<<dim3(64, 2), 256, 131072>>>();
    k_att<<<BN, 128>>>(mask);
    k_out<<<BN, 64>>>(Wout, (float*)d_out);
}

// round 12
// speedup vs baseline: 2.6102x; 1.0348x over previous
#include <cuda_runtime.h>
#include <cuda_fp16.h>
#include <cstdint>

// L2DistAttention — round 12 (byte-identical resubmit; rounds 7-11 hit
// GPUAcquisitionTimeout): mma.sync fp16 2-split, 3 terms (main @ f32-accum
// + 2 corrections @ f16-accum 2x rate). tcgen05 unavailable (harness
// targets base sm_103). k_fold+k_radial fused; k_att+k_out fused.

#define BN   512
#define NE   8192
#define DD   64
#define HID  128
#define KVD  256
#define RH   64
#define KROWS 4160

__device__ float g_q  [BN*HID];
__device__ float g_xi [BN*DD];
__device__ float g_xj [BN*DD];
__device__ float g_xe [NE*DD];
__device__ float g_hdd[NE*RH];
__device__ __half g_Whi[KROWS*KVD];
__device__ __half g_Wlo[KROWS*KVD];
__device__ float g_kv [NE*KVD];
__device__ int   g_maskmode;

// ------------------------------------------------------------------ helpers
__device__ __forceinline__ uint32_t smem_u32(const void* p) {
    return (uint32_t)__cvta_generic_to_shared(p);
}
__device__ __forceinline__ void ldsm4(uint32_t& r0, uint32_t& r1, uint32_t& r2, uint32_t& r3,
                                      uint32_t addr) {
    asm volatile("ldmatrix.sync.aligned.m8n8.x4.shared.b16 {%0,%1,%2,%3}, [%4];"
                 : "=r"(r0), "=r"(r1), "=r"(r2), "=r"(r3) : "r"(addr));
}
__device__ __forceinline__ void ldsm4t(uint32_t& r0, uint32_t& r1, uint32_t& r2, uint32_t& r3,
                                       uint32_t addr) {
    asm volatile("ldmatrix.sync.aligned.m8n8.x4.trans.shared.b16 {%0,%1,%2,%3}, [%4];"
                 : "=r"(r0), "=r"(r1), "=r"(r2), "=r"(r3) : "r"(addr));
}
// main term: f16 x f16 -> f32 accum
__device__ __forceinline__ void mma_f32(float* c, const uint32_t* a, const uint32_t* b) {
    asm volatile("mma.sync.aligned.m16n8k16.row.col.f32.f16.f16.f32 "
                 "{%0,%1,%2,%3},{%4,%5,%6,%7},{%8,%9},{%0,%1,%2,%3};"
                 : "+f"(c[0]), "+f"(c[1]), "+f"(c[2]), "+f"(c[3])
                 : "r"(a[0]), "r"(a[1]), "r"(a[2]), "r"(a[3]), "r"(b[0]), "r"(b[1]));
}
// correction terms: f16 x f16 -> f16 accum (2x rate)
__device__ __forceinline__ void mma_f16(uint32_t* c, const uint32_t* a, const uint32_t* b) {
    asm volatile("mma.sync.aligned.m16n8k16.row.col.f16.f16.f16.f16 "
                 "{%0,%1},{%2,%3,%4,%5},{%6,%7},{%0,%1};"
                 : "+r"(c[0]), "+r"(c[1])
                 : "r"(a[0]), "r"(a[1]), "r"(a[2]), "r"(a[3]), "r"(b[0]), "r"(b[1]));
}
__device__ __forceinline__ uint32_t packh(__half a, __half b) {
    return (uint32_t)__half_as_ushort(a) | ((uint32_t)__half_as_ushort(b) << 16);
}

// ------------------------------------- prenorm + projections (+mask detect)
__global__ void k_prenorm_proj(const float* __restrict__ feat,
                               const float* __restrict__ gamma,
                               const float* __restrict__ Wq,
                               const float* __restrict__ Wxi,
                               const float* __restrict__ Wxj,
                               const unsigned char* __restrict__ mb) {
    __shared__ float xs[DD];
    __shared__ float red[256];
    __shared__ float sinv;
    int t = threadIdx.x;  // 256
    if (blockIdx.x == BN) {                     // mask-dtype detection block
        int s = 0;
        for (int i = t; i < 8192; i += 256) s += mb[i];
        ((int*)red)[t] = s; __syncthreads();
        for (int o = 128; o; o >>= 1) { if (t < o) ((int*)red)[t] += ((int*)red)[t+o]; __syncthreads(); }
        if (t == 0) {
            int tot = ((int*)red)[0];
            g_maskmode = (tot > 100000) ? 2 : ((tot > 4000) ? 0 : 1);
        }
        return;
    }
    int node = blockIdx.x;
    if (t < 64) { float f = feat[node*64 + t]; red[t] = f*f; }
    __syncthreads();
    if (t < 32) {
        float v = red[t] + red[t+32];
        for (int o = 16; o; o >>= 1) v += __shfl_xor_sync(0xffffffffu, v, o);
        if (t == 0) {
            float rms = sqrtf(v) * 0.125f;
            sinv = 1.0f / fmaxf(rms, 1e-12f);
        }
    }
    __syncthreads();
    if (t < 64) xs[t] = feat[node*64 + t] * sinv * gamma[t];
    __syncthreads();
    if (t < 128) {
        float acc = 0.f;
        #pragma unroll 16
        for (int d = 0; d < 64; d++) acc = fmaf(xs[d], Wq[d*128 + t], acc);
        g_q[node*128 + t] = acc;
    } else if (t < 192) {
        int c = t - 128; float acc = 0.f;
        #pragma unroll 16
        for (int d = 0; d < 64; d++) acc = fmaf(xs[d], Wxi[d*64 + c], acc);
        g_xi[node*64 + c] = acc;
    } else {
        int c = t - 192; float acc = 0.f;
        #pragma unroll 16
        for (int d = 0; d < 64; d++) acc = fmaf(xs[d], Wxj[d*64 + c], acc);
        g_xj[node*64 + c] = acc;
    }
}

// ---------------------------------------------------------------- edge gather
__global__ void k_xe(const int* __restrict__ nidx) {
    int i = blockIdx.x * 256 + threadIdx.x;
    int e = i >> 6, d = i & 63;
    int node = e >> 4;
    int b    = node >> 8;
    int nb   = nidx[e];
    g_xe[i] = g_xj[(b*256 + nb)*64 + d] + g_xi[node*64 + d];
}

// ------------- fused: fold (blocks 0..259) + radial MLP (blocks 260..1283)
__global__ void __launch_bounds__(256) k_fold_radial(
        const float* __restrict__ W3,  const float* __restrict__ b3,
        const float* __restrict__ Wkv,
        const float* __restrict__ rel,
        const float* __restrict__ W1,  const float* __restrict__ b1,
        const float* __restrict__ g1,
        const float* __restrict__ W2,  const float* __restrict__ b2,
        const float* __restrict__ g2) {
    __shared__ float sbuf[8192];   // 32KB: fold uses all, radial first 16KB
    int tid = threadIdx.x;

    if (blockIdx.x < 260) {
        // ---------------- fold: W3f = [rp_W3 ; b3] @ Wkv_out -> fp16 hi/lo
        float (*As)[64]  = (float(*)[64])sbuf;
        float (*Bsh)[64] = (float(*)[64])(sbuf + 4096);
        int tx = tid & 15, ty = tid >> 4;
        int fb = blockIdx.x;
        int mb = fb % 65;           // 0..64 (64 = bias block)
        int ob = (fb / 65) * 64;
        float acc[4][4] = {};
        for (int kc = 0; kc < 256; kc += 64) {
            __syncthreads();
            #pragma unroll
            for (int q = 0; q < 4; q++) {
                int f4 = tid + 256*q; int kl = f4 >> 4; int d4 = (f4 & 15) * 4;
                float4 av;
                if (mb < 64) av = *(const float4*)&W3[(size_t)mb*16384 + (size_t)(kc+kl)*64 + d4];
                else         av = *(const float4*)&b3[(size_t)(kc+kl)*64 + d4];
                *(float4*)&As[kl][d4] = av;
                *(float4*)&Bsh[kl][d4] = *(const float4*)&Wkv[(size_t)(kc+kl)*256 + ob + d4];
            }
            __syncthreads();
            #pragma unroll 16
            for (int k = 0; k < 64; k++) {
                float4 a4 = *(const float4*)&As[k][ty*4];
                float4 b4 = *(const float4*)&Bsh[k][tx*4];
                acc[0][0]=fmaf(a4.x,b4.x,acc[0][0]); acc[0][1]=fmaf(a4.x,b4.y,acc[0][1]);
                acc[0][2]=fmaf(a4.x,b4.z,acc[0][2]); acc[0][3]=fmaf(a4.x,b4.w,acc[0][3]);
                acc[1][0]=fmaf(a4.y,b4.x,acc[1][0]); acc[1][1]=fmaf(a4.y,b4.y,acc[1][1]);
                acc[1][2]=fmaf(a4.y,b4.z,acc[1][2]); acc[1][3]=fmaf(a4.y,b4.w,acc[1][3]);
                acc[2][0]=fmaf(a4.z,b4.x,acc[2][0]); acc[2][1]=fmaf(a4.z,b4.y,acc[2][1]);
                acc[2][2]=fmaf(a4.z,b4.z,acc[2][2]); acc[2][3]=fmaf(a4.z,b4.w,acc[2][3]);
                acc[3][0]=fmaf(a4.w,b4.x,acc[3][0]); acc[3][1]=fmaf(a4.w,b4.y,acc[3][1]);
                acc[3][2]=fmaf(a4.w,b4.z,acc[3][2]); acc[3][3]=fmaf(a4.w,b4.w,acc[3][3]);
            }
        }
        #pragma unroll
        for (int i = 0; i < 4; i++) {
            size_t row = (size_t)(mb*64 + ty*4 + i);
            __half h[4], l[4];
            #pragma unroll
            for (int j = 0; j < 4; j++) {
                h[j] = __float2half_rn(acc[i][j]);
                l[j] = __float2half_rn(acc[i][j] - __half2float(h[j]));
            }
            uint32_t* ph = (uint32_t*)&g_Whi[row*256 + ob + tx*4];
            uint32_t* pl = (uint32_t*)&g_Wlo[row*256 + ob + tx*4];
            ph[0] = packh(h[0], h[1]); ph[1] = packh(h[2], h[3]);
            pl[0] = packh(l[0], l[1]); pl[1] = packh(l[2], l[3]);
        }
        return;
    }

    // ---------------- radial MLP: warp per edge
    float* sW2 = sbuf;             // 16KB
    int lane = tid & 31, w = tid >> 5;
    for (int i = tid; i < RH*RH; i += 256) sW2[i] = W2[i];
    __syncthreads();
    int e = (blockIdx.x - 260) * 8 + w;
    int c0 = lane * 2, c1 = c0 + 1;
    float s = rel[e];
    float a0 = fmaf(s, W1[c0], b1[c0]);
    float a1 = fmaf(s, W1[c1], b1[c1]);
    float h0 = a0 / (1.0f + __expf(-a0));
    float h1 = a1 / (1.0f + __expf(-a1));
    float sum = h0 + h1;
    #pragma unroll
    for (int o = 16; o; o >>= 1) sum += __shfl_xor_sync(0xffffffffu, sum, o);
    float mean = sum * (1.0f/64.0f);
    float d0 = h0 - mean, d1 = h1 - mean;
    float v = d0*d0 + d1*d1;
    #pragma unroll
    for (int o = 16; o; o >>= 1) v += __shfl_xor_sync(0xffffffffu, v, o);
    float rstd = rsqrtf(v * (1.0f/64.0f) + 1e-5f);
    float y0 = d0 * rstd * g1[c0];
    float y1 = d1 * rstd * g1[c1];
    float o0 = b2[c0], o1 = b2[c1];
    #pragma unroll 8
    for (int r2 = 0; r2 < 32; r2++) {
        float yr0 = __shfl_sync(0xffffffffu, y0, r2);
        float yr1 = __shfl_sync(0xffffffffu, y1, r2);
        float2 w0 = *(const float2*)&sW2[(2*r2  )*64 + c0];
        float2 w1 = *(const float2*)&sW2[(2*r2+1)*64 + c0];
        o0 = fmaf(yr0, w0.x, fmaf(yr1, w1.x, o0));
        o1 = fmaf(yr0, w0.y, fmaf(yr1, w1.y, o1));
    }
    float h20 = o0 / (1.0f + __expf(-o0));
    float h21 = o1 / (1.0f + __expf(-o1));
    sum = h20 + h21;
    #pragma unroll
    for (int o = 16; o; o >>= 1) sum += __shfl_xor_sync(0xffffffffu, sum, o);
    mean = sum * (1.0f/64.0f);
    d0 = h20 - mean; d1 = h21 - mean;
    v = d0*d0 + d1*d1;
    #pragma unroll
    for (int o = 16; o; o >>= 1) v += __shfl_xor_sync(0xffffffffu, v, o);
    rstd = rsqrtf(v * (1.0f/64.0f) + 1e-5f);
    float2 outv = make_float2(d0 * rstd * g2[c0], d1 * rstd * g2[c1]);
    *(float2*)&g_hdd[e*64 + c0] = outv;
}

// ---------------- main z-GEMM: kv = z @ W3f ; fp16 2-split, 3 terms
// (hi*hi -> f32 acc ; lo*hi + hi*lo -> f16 acc at 2x rate)
__global__ void __launch_bounds__(256) k_main() {
    extern __shared__ char sm[];
    float* s_hT = (float*)sm;                 // [64 r][128 m]  32KB
    char*  sA   = sm + 32768;                 // A_hi 16KB | A_lo 16KB
    char*  sB   = sm + 65536;                 // 2 stages x (B_hi 16KB | B_lo 16KB)

    int tid  = threadIdx.x;
    int lane = tid & 31, warp = tid >> 5;
    int wm = warp & 3, wn = warp >> 2;        // 4 x 2 warp grid
    int eb = blockIdx.x * 128, ob = blockIdx.y * 128;

    auto cpB = [&](int stage, int chunk) {
        char* st = sB + stage * 32768;
        #pragma unroll
        for (int i = 0; i < 8; i++) {
            int f = i * 256 + tid;            // 0..2047 16B granules
            int tile = f >> 10;               // 0=hi 1=lo
            int k    = (f >> 4) & 63;
            int gn   = f & 15;
            const __half* src =
                (tile ? g_Wlo : g_Whi) + (size_t)(chunk*64 + k)*256 + ob + gn*8;
            uint32_t dst = smem_u32(st + tile*16384 + k*256 + ((gn ^ (k & 7)) * 16));
            asm volatile("cp.async.cg.shared.global [%0], [%1], 16;" :: "r"(dst), "l"(src));
        }
        asm volatile("cp.async.commit_group;");
    };

    cpB(0, 0);

    // xe row slice in registers: thread t -> row zm, cols zd..zd+31
    int zm = tid >> 1, zd = (tid & 1) * 32;
    float xr[32];
    #pragma unroll
    for (int j = 0; j < 32; j += 4)
        *(float4*)&xr[j] = *(const float4*)&g_xe[(size_t)(eb + zm)*64 + zd + j];

    // hdd tile transposed into smem
    for (int idx = tid; idx < 8192; idx += 256) {
        int rr = idx >> 7, m = idx & 127;
        s_hT[idx] = g_hdd[(size_t)(eb + m)*64 + rr];
    }

    float    acc [2][8][4];
    uint32_t hacc[2][8][2];
    #pragma unroll
    for (int a = 0; a < 2; a++)
        #pragma unroll
        for (int b = 0; b < 8; b++) {
            #pragma unroll
            for (int c = 0; c < 4; c++) acc[a][b][c] = 0.f;
            hacc[a][b][0] = 0u; hacc[a][b][1] = 0u;
        }

    uint32_t aAhi = smem_u32(sA);
    uint32_t aAlo = aAhi + 16384;
    uint32_t rowA = (uint32_t)zm * 128;
    int      swm  = zm & 7;

    for (int r = 0; r < 65; ++r) {
        asm volatile("cp.async.wait_group 0;");
        __syncthreads();                       // B[r] visible; previous mma done
        if (r + 1 < 65) cpB((r + 1) & 1, r + 1);

        // z = h * xe, split to fp16 hi/lo tiles
        float h = (r < 64) ? s_hT[r*128 + zm] : 1.0f;
        #pragma unroll
        for (int j = 0; j < 32; j += 2) {
            float z0 = h * xr[j], z1 = h * xr[j+1];
            __half h0 = __float2half_rn(z0);
            __half h1 = __float2half_rn(z1);
            __half l0 = __float2half_rn(z0 - __half2float(h0));
            __half l1 = __float2half_rn(z1 - __half2float(h1));
            int d = zd + j;
            uint32_t off = rowA + (((d >> 3) ^ swm) << 4) + ((d & 7) * 2);
            *(uint32_t*)(sA + off)         = packh(h0, h1);
            *(uint32_t*)(sA + 16384 + off) = packh(l0, l1);
        }
        __syncthreads();                       // A tiles ready

        char* st = sB + (r & 1) * 32768;
        uint32_t aBhi = smem_u32(st);
        uint32_t aBlo = aBhi + 16384;
        #pragma unroll
        for (int ks = 0; ks < 4; ++ks) {
            uint32_t ahi[2][4], alo[2][4];
            #pragma unroll
            for (int mt = 0; mt < 2; ++mt) {
                int rrow = wm*32 + mt*16 + (lane & 7) + ((lane >> 3) & 1) * 8;
                int g    = ks*2 + ((lane >> 4) & 1);
                uint32_t off = rrow*128 + ((g ^ (rrow & 7)) << 4);
                ldsm4(ahi[mt][0], ahi[mt][1], ahi[mt][2], ahi[mt][3], aAhi + off);
                ldsm4(alo[mt][0], alo[mt][1], alo[mt][2], alo[mt][3], aAlo + off);
            }
            #pragma unroll
            for (int p = 0; p < 4; ++p) {
                int krow = ks*16 + (lane & 7) + ((lane >> 3) & 1) * 8;
                int ncol = wn*64 + p*16 + ((lane >> 4) & 1) * 8;
                uint32_t off = krow*256 + ((((ncol >> 3) ^ (krow & 7))) << 4);
                uint32_t bhi[4], blo[4];
                ldsm4t(bhi[0], bhi[1], bhi[2], bhi[3], aBhi + off);
                ldsm4t(blo[0], blo[1], blo[2], blo[3], aBlo + off);
                #pragma unroll
                for (int mt = 0; mt < 2; ++mt) {
                    mma_f32(acc [mt][2*p],   ahi[mt], bhi);
                    mma_f16(hacc[mt][2*p],   alo[mt], bhi);
                    mma_f16(hacc[mt][2*p],   ahi[mt], blo);
                    mma_f32(acc [mt][2*p+1], ahi[mt], bhi + 2);
                    mma_f16(hacc[mt][2*p+1], alo[mt], bhi + 2);
                    mma_f16(hacc[mt][2*p+1], ahi[mt], blo + 2);
                }
            }
        }
    }

    // epilogue: combine f32 + f16 accumulators, write fp32 kv
    int gq = lane >> 2, t4 = lane & 3;
    #pragma unroll
    for (int mt = 0; mt < 2; ++mt) {
        #pragma unroll
        for (int ng = 0; ng < 8; ++ng) {
            __half2 q0 = *(__half2*)&hacc[mt][ng][0];
            __half2 q1 = *(__half2*)&hacc[mt][ng][1];
            float2 c01 = __half22float2(q0);
            float2 c23 = __half22float2(q1);
            int row = eb + wm*32 + mt*16 + gq;
            int col = ob + wn*64 + ng*8 + t4*2;
            *(float2*)&g_kv[(size_t)row*256 + col] =
                make_float2(acc[mt][ng][0] + c01.x, acc[mt][ng][1] + c01.y);
            *(float2*)&g_kv[(size_t)(row + 8)*256 + col] =
                make_float2(acc[mt][ng][2] + c23.x, acc[mt][ng][3] + c23.y);
        }
    }
}

// ------------------------------------------- attention + out-proj (fused)
__global__ void k_attout(const void* __restrict__ maskbuf,
                         const float* __restrict__ Wout,
                         float* __restrict__ out) {
    __shared__ float ao[HID];
    int node = blockIdx.x;
    int h = threadIdx.x >> 5, l = threadIdx.x & 31;
    float qv = g_q[node*128 + h*32 + l];
    int mode = g_maskmode;
    int ebase = node * 16;
    float sim[16];
    #pragma unroll
    for (int j = 0; j < 16; j++) {
        int e = ebase + j;
        float kvv = g_kv[(size_t)e*256 + h*32 + l];
        float df = qv - kvv + 1e-6f;
        float s = df * df;
        #pragma unroll
        for (int o = 16; o; o >>= 1) s += __shfl_xor_sync(0xffffffffu, s, o);
        bool m;
        if      (mode == 0) m = ((const unsigned char*)maskbuf)[e] != 0;
        else if (mode == 1) m = ((const int*)maskbuf)[e] != 0;
        else                m = ((const float*)maskbuf)[e] != 0.0f;
        sim[j] = m ? (-sqrtf(s) * 0.17677669529663687f)
                   : -3.4028234663852886e38f;
    }
    float mx = sim[0];
    #pragma unroll
    for (int j = 1; j < 16; j++) mx = fmaxf(mx, sim[j]);
    float w[16], Z = 0.f;
    #pragma unroll
    for (int j = 0; j < 16; j++) { w[j] = __expf(sim[j] - mx); Z += w[j]; }
    float inv = 1.0f / Z;
    float o = 0.f;
    #pragma unroll
    for (int j = 0; j < 16; j++)
        o = fmaf(w[j] * inv, g_kv[(size_t)(ebase+j)*256 + 128 + h*32 + l], o);
    ao[h*32 + l] = o;
    __syncthreads();
    int t = threadIdx.x;
    if (t < 64) {
        float acc = 0.f;
        #pragma unroll 16
        for (int i = 0; i < 128; i++) acc = fmaf(ao[i], Wout[i*64 + t], acc);
        out[node*64 + t] = acc;
    }
}

// -------------------------------------------------------------------- launch
extern "C" void kernel_launch(void* const* d_in, const int* in_sizes, int n_in,
                              void* d_out, int out_size) {
    const float* feat  = (const float*)d_in[0];
    const int*   nidx  = (const int*)  d_in[1];
    const void*  mask  =               d_in[2];
    const float* rel   = (const float*)d_in[3];
    const float* gamma = (const float*)d_in[4];
    const float* Wq    = (const float*)d_in[5];
    const float* Wxi   = (const float*)d_in[6];
    const float* Wxj   = (const float*)d_in[7];
    const float* W1    = (const float*)d_in[8];
    const float* b1    = (const float*)d_in[9];
    const float* g1    = (const float*)d_in[10];
    const float* W2    = (const float*)d_in[11];
    const float* b2    = (const float*)d_in[12];
    const float* g2    = (const float*)d_in[13];
    const float* W3    = (const float*)d_in[14];
    const float* b3    = (const float*)d_in[15];
    const float* Wkv   = (const float*)d_in[16];
    const float* Wout  = (const float*)d_in[17];

    cudaFuncSetAttribute(k_main, cudaFuncAttributeMaxDynamicSharedMemorySize, 131072);

    k_prenorm_proj<<<BN + 1, 256>>>(feat, gamma, Wq, Wxi, Wxj,
                                    (const unsigned char*)mask);
    k_xe<<<NE*DD/256, 256>>>(nidx);
    k_fold_radial<<<260 + NE/8, 256>>>(W3, b3, Wkv, rel, W1, b1, g1, W2, b2, g2);
    k_main<<<dim3(64, 2), 256, 131072>>>();
    k_attout<<<BN, 128>>>(mask, Wout, (float*)d_out);
}

// round 17
// speedup vs baseline: 2.6866x; 1.0293x over previous
#include <cuda_runtime.h>
#include <cuda_fp16.h>
#include <cstdint>

// L2DistAttention — round 17 (byte-identical resubmit of round-13..16; benches
// hit GPUAcquisitionTimeout): software-pipelined k_main. A double-buffered;
// z-split for chunk r+1 issued AFTER mma of chunk r (overlaps with tensor
// drain); ONE __syncthreads per chunk. Math order unchanged -> rel_err
// should match round-12 (6.7e-6).

#define BN   512
#define NE   8192
#define DD   64
#define HID  128
#define KVD  256
#define RH   64
#define KROWS 4160

__device__ float g_q  [BN*HID];
__device__ float g_xi [BN*DD];
__device__ float g_xj [BN*DD];
__device__ float g_xe [NE*DD];
__device__ float g_hdd[NE*RH];
__device__ __half g_Whi[KROWS*KVD];
__device__ __half g_Wlo[KROWS*KVD];
__device__ float g_kv [NE*KVD];
__device__ int   g_maskmode;

// ------------------------------------------------------------------ helpers
__device__ __forceinline__ uint32_t smem_u32(const void* p) {
    return (uint32_t)__cvta_generic_to_shared(p);
}
__device__ __forceinline__ void ldsm4(uint32_t& r0, uint32_t& r1, uint32_t& r2, uint32_t& r3,
                                      uint32_t addr) {
    asm volatile("ldmatrix.sync.aligned.m8n8.x4.shared.b16 {%0,%1,%2,%3}, [%4];"
                 : "=r"(r0), "=r"(r1), "=r"(r2), "=r"(r3) : "r"(addr));
}
__device__ __forceinline__ void ldsm4t(uint32_t& r0, uint32_t& r1, uint32_t& r2, uint32_t& r3,
                                       uint32_t addr) {
    asm volatile("ldmatrix.sync.aligned.m8n8.x4.trans.shared.b16 {%0,%1,%2,%3}, [%4];"
                 : "=r"(r0), "=r"(r1), "=r"(r2), "=r"(r3) : "r"(addr));
}
// main term: f16 x f16 -> f32 accum
__device__ __forceinline__ void mma_f32(float* c, const uint32_t* a, const uint32_t* b) {
    asm volatile("mma.sync.aligned.m16n8k16.row.col.f32.f16.f16.f32 "
                 "{%0,%1,%2,%3},{%4,%5,%6,%7},{%8,%9},{%0,%1,%2,%3};"
                 : "+f"(c[0]), "+f"(c[1]), "+f"(c[2]), "+f"(c[3])
                 : "r"(a[0]), "r"(a[1]), "r"(a[2]), "r"(a[3]), "r"(b[0]), "r"(b[1]));
}
// correction terms: f16 x f16 -> f16 accum
__device__ __forceinline__ void mma_f16(uint32_t* c, const uint32_t* a, const uint32_t* b) {
    asm volatile("mma.sync.aligned.m16n8k16.row.col.f16.f16.f16.f16 "
                 "{%0,%1},{%2,%3,%4,%5},{%6,%7},{%0,%1};"
                 : "+r"(c[0]), "+r"(c[1])
                 : "r"(a[0]), "r"(a[1]), "r"(a[2]), "r"(a[3]), "r"(b[0]), "r"(b[1]));
}
__device__ __forceinline__ uint32_t packh(__half a, __half b) {
    return (uint32_t)__half_as_ushort(a) | ((uint32_t)__half_as_ushort(b) << 16);
}

// ------------------------------------- prenorm + projections (+mask detect)
__global__ void k_prenorm_proj(const float* __restrict__ feat,
                               const float* __restrict__ gamma,
                               const float* __restrict__ Wq,
                               const float* __restrict__ Wxi,
                               const float* __restrict__ Wxj,
                               const unsigned char* __restrict__ mb) {
    __shared__ float xs[DD];
    __shared__ float red[256];
    __shared__ float sinv;
    int t = threadIdx.x;  // 256
    if (blockIdx.x == BN) {                     // mask-dtype detection block
        int s = 0;
        for (int i = t; i < 8192; i += 256) s += mb[i];
        ((int*)red)[t] = s; __syncthreads();
        for (int o = 128; o; o >>= 1) { if (t < o) ((int*)red)[t] += ((int*)red)[t+o]; __syncthreads(); }
        if (t == 0) {
            int tot = ((int*)red)[0];
            g_maskmode = (tot > 100000) ? 2 : ((tot > 4000) ? 0 : 1);
        }
        return;
    }
    int node = blockIdx.x;
    if (t < 64) { float f = feat[node*64 + t]; red[t] = f*f; }
    __syncthreads();
    if (t < 32) {
        float v = red[t] + red[t+32];
        for (int o = 16; o; o >>= 1) v += __shfl_xor_sync(0xffffffffu, v, o);
        if (t == 0) {
            float rms = sqrtf(v) * 0.125f;
            sinv = 1.0f / fmaxf(rms, 1e-12f);
        }
    }
    __syncthreads();
    if (t < 64) xs[t] = feat[node*64 + t] * sinv * gamma[t];
    __syncthreads();
    if (t < 128) {
        float acc = 0.f;
        #pragma unroll 16
        for (int d = 0; d < 64; d++) acc = fmaf(xs[d], Wq[d*128 + t], acc);
        g_q[node*128 + t] = acc;
    } else if (t < 192) {
        int c = t - 128; float acc = 0.f;
        #pragma unroll 16
        for (int d = 0; d < 64; d++) acc = fmaf(xs[d], Wxi[d*64 + c], acc);
        g_xi[node*64 + c] = acc;
    } else {
        int c = t - 192; float acc = 0.f;
        #pragma unroll 16
        for (int d = 0; d < 64; d++) acc = fmaf(xs[d], Wxj[d*64 + c], acc);
        g_xj[node*64 + c] = acc;
    }
}

// ---------------------------------------------------------------- edge gather
__global__ void k_xe(const int* __restrict__ nidx) {
    int i = blockIdx.x * 256 + threadIdx.x;
    int e = i >> 6, d = i & 63;
    int node = e >> 4;
    int b    = node >> 8;
    int nb   = nidx[e];
    g_xe[i] = g_xj[(b*256 + nb)*64 + d] + g_xi[node*64 + d];
}

// ------------- fused: fold (blocks 0..259) + radial MLP (blocks 260..1283)
__global__ void __launch_bounds__(256) k_fold_radial(
        const float* __restrict__ W3,  const float* __restrict__ b3,
        const float* __restrict__ Wkv,
        const float* __restrict__ rel,
        const float* __restrict__ W1,  const float* __restrict__ b1,
        const float* __restrict__ g1,
        const float* __restrict__ W2,  const float* __restrict__ b2,
        const float* __restrict__ g2) {
    __shared__ float sbuf[8192];   // 32KB: fold uses all, radial first 16KB
    int tid = threadIdx.x;

    if (blockIdx.x < 260) {
        // ---------------- fold: W3f = [rp_W3 ; b3] @ Wkv_out -> fp16 hi/lo
        float (*As)[64]  = (float(*)[64])sbuf;
        float (*Bsh)[64] = (float(*)[64])(sbuf + 4096);
        int tx = tid & 15, ty = tid >> 4;
        int fb = blockIdx.x;
        int mb = fb % 65;           // 0..64 (64 = bias block)
        int ob = (fb / 65) * 64;
        float acc[4][4] = {};
        for (int kc = 0; kc < 256; kc += 64) {
            __syncthreads();
            #pragma unroll
            for (int q = 0; q < 4; q++) {
                int f4 = tid + 256*q; int kl = f4 >> 4; int d4 = (f4 & 15) * 4;
                float4 av;
                if (mb < 64) av = *(const float4*)&W3[(size_t)mb*16384 + (size_t)(kc+kl)*64 + d4];
                else         av = *(const float4*)&b3[(size_t)(kc+kl)*64 + d4];
                *(float4*)&As[kl][d4] = av;
                *(float4*)&Bsh[kl][d4] = *(const float4*)&Wkv[(size_t)(kc+kl)*256 + ob + d4];
            }
            __syncthreads();
            #pragma unroll 16
            for (int k = 0; k < 64; k++) {
                float4 a4 = *(const float4*)&As[k][ty*4];
                float4 b4 = *(const float4*)&Bsh[k][tx*4];
                acc[0][0]=fmaf(a4.x,b4.x,acc[0][0]); acc[0][1]=fmaf(a4.x,b4.y,acc[0][1]);
                acc[0][2]=fmaf(a4.x,b4.z,acc[0][2]); acc[0][3]=fmaf(a4.x,b4.w,acc[0][3]);
                acc[1][0]=fmaf(a4.y,b4.x,acc[1][0]); acc[1][1]=fmaf(a4.y,b4.y,acc[1][1]);
                acc[1][2]=fmaf(a4.y,b4.z,acc[1][2]); acc[1][3]=fmaf(a4.y,b4.w,acc[1][3]);
                acc[2][0]=fmaf(a4.z,b4.x,acc[2][0]); acc[2][1]=fmaf(a4.z,b4.y,acc[2][1]);
                acc[2][2]=fmaf(a4.z,b4.z,acc[2][2]); acc[2][3]=fmaf(a4.z,b4.w,acc[2][3]);
                acc[3][0]=fmaf(a4.w,b4.x,acc[3][0]); acc[3][1]=fmaf(a4.w,b4.y,acc[3][1]);
                acc[3][2]=fmaf(a4.w,b4.z,acc[3][2]); acc[3][3]=fmaf(a4.w,b4.w,acc[3][3]);
            }
        }
        #pragma unroll
        for (int i = 0; i < 4; i++) {
            size_t row = (size_t)(mb*64 + ty*4 + i);
            __half h[4], l[4];
            #pragma unroll
            for (int j = 0; j < 4; j++) {
                h[j] = __float2half_rn(acc[i][j]);
                l[j] = __float2half_rn(acc[i][j] - __half2float(h[j]));
            }
            uint32_t* ph = (uint32_t*)&g_Whi[row*256 + ob + tx*4];
            uint32_t* pl = (uint32_t*)&g_Wlo[row*256 + ob + tx*4];
            ph[0] = packh(h[0], h[1]); ph[1] = packh(h[2], h[3]);
            pl[0] = packh(l[0], l[1]); pl[1] = packh(l[2], l[3]);
        }
        return;
    }

    // ---------------- radial MLP: warp per edge
    float* sW2 = sbuf;             // 16KB
    int lane = tid & 31, w = tid >> 5;
    for (int i = tid; i < RH*RH; i += 256) sW2[i] = W2[i];
    __syncthreads();
    int e = (blockIdx.x - 260) * 8 + w;
    int c0 = lane * 2, c1 = c0 + 1;
    float s = rel[e];
    float a0 = fmaf(s, W1[c0], b1[c0]);
    float a1 = fmaf(s, W1[c1], b1[c1]);
    float h0 = a0 / (1.0f + __expf(-a0));
    float h1 = a1 / (1.0f + __expf(-a1));
    float sum = h0 + h1;
    #pragma unroll
    for (int o = 16; o; o >>= 1) sum += __shfl_xor_sync(0xffffffffu, sum, o);
    float mean = sum * (1.0f/64.0f);
    float d0 = h0 - mean, d1 = h1 - mean;
    float v = d0*d0 + d1*d1;
    #pragma unroll
    for (int o = 16; o; o >>= 1) v += __shfl_xor_sync(0xffffffffu, v, o);
    float rstd = rsqrtf(v * (1.0f/64.0f) + 1e-5f);
    float y0 = d0 * rstd * g1[c0];
    float y1 = d1 * rstd * g1[c1];
    float o0 = b2[c0], o1 = b2[c1];
    #pragma unroll 8
    for (int r2 = 0; r2 < 32; r2++) {
        float yr0 = __shfl_sync(0xffffffffu, y0, r2);
        float yr1 = __shfl_sync(0xffffffffu, y1, r2);
        float2 w0 = *(const float2*)&sW2[(2*r2  )*64 + c0];
        float2 w1 = *(const float2*)&sW2[(2*r2+1)*64 + c0];
        o0 = fmaf(yr0, w0.x, fmaf(yr1, w1.x, o0));
        o1 = fmaf(yr0, w0.y, fmaf(yr1, w1.y, o1));
    }
    float h20 = o0 / (1.0f + __expf(-o0));
    float h21 = o1 / (1.0f + __expf(-o1));
    sum = h20 + h21;
    #pragma unroll
    for (int o = 16; o; o >>= 1) sum += __shfl_xor_sync(0xffffffffu, sum, o);
    mean = sum * (1.0f/64.0f);
    d0 = h20 - mean; d1 = h21 - mean;
    v = d0*d0 + d1*d1;
    #pragma unroll
    for (int o = 16; o; o >>= 1) v += __shfl_xor_sync(0xffffffffu, v, o);
    rstd = rsqrtf(v * (1.0f/64.0f) + 1e-5f);
    float2 outv = make_float2(d0 * rstd * g2[c0], d1 * rstd * g2[c1]);
    *(float2*)&g_hdd[e*64 + c0] = outv;
}

// ---------------- main z-GEMM: kv = z @ W3f ; fp16 2-split, 3 terms
// Pipelined: A double-buffered, one __syncthreads per chunk; z-split for
// chunk r+1 issued after mma of chunk r (overlaps tensor drain).
// SMEM: [0,32K) hT ; [32K,96K) A 2st x (hi|lo) ; [96K,160K) B 2st x (hi|lo)
#define SM_TOTAL_MAIN 163840

__global__ void __launch_bounds__(256) k_main() {
    extern __shared__ char sm[];
    float* s_hT = (float*)sm;                 // [64 r][128 m]  32KB
    char*  sA   = sm + 32768;                 // 2 stages x (hi 16K | lo 16K)
    char*  sB   = sm + 98304;                 // 2 stages x (hi 16K | lo 16K)

    int tid  = threadIdx.x;
    int lane = tid & 31, warp = tid >> 5;
    int wm = warp & 3, wn = warp >> 2;        // 4 x 2 warp grid
    int eb = blockIdx.x * 128, ob = blockIdx.y * 128;

    auto cpB = [&](int stage, int chunk) {
        char* st = sB + stage * 32768;
        #pragma unroll
        for (int i = 0; i < 8; i++) {
            int f = i * 256 + tid;            // 0..2047 16B granules
            int tile = f >> 10;               // 0=hi 1=lo
            int k    = (f >> 4) & 63;
            int gn   = f & 15;
            const __half* src =
                (tile ? g_Wlo : g_Whi) + (size_t)(chunk*64 + k)*256 + ob + gn*8;
            uint32_t dst = smem_u32(st + tile*16384 + k*256 + ((gn ^ (k & 7)) * 16));
            asm volatile("cp.async.cg.shared.global [%0], [%1], 16;" :: "r"(dst), "l"(src));
        }
        asm volatile("cp.async.commit_group;");
    };

    cpB(0, 0);

    // xe row slice in registers: thread t -> row zm, cols zd..zd+31
    int zm = tid >> 1, zd = (tid & 1) * 32;
    float xr[32];
    #pragma unroll
    for (int j = 0; j < 32; j += 4)
        *(float4*)&xr[j] = *(const float4*)&g_xe[(size_t)(eb + zm)*64 + zd + j];

    // hdd tile transposed into smem
    for (int idx = tid; idx < 8192; idx += 256) {
        int rr = idx >> 7, m = idx & 127;
        s_hT[idx] = g_hdd[(size_t)(eb + m)*64 + rr];
    }
    __syncthreads();                           // s_hT ready for computeA(0)

    uint32_t rowA = (uint32_t)zm * 128;
    int      swm  = zm & 7;

    // z = h * xe -> fp16 hi/lo into A stage (rr & 1)
    auto computeA = [&](int rr) {
        char* aSt = sA + (rr & 1) * 32768;
        float h = (rr < 64) ? s_hT[rr*128 + zm] : 1.0f;
        #pragma unroll
        for (int j = 0; j < 32; j += 2) {
            float z0 = h * xr[j], z1 = h * xr[j+1];
            __half h0 = __float2half_rn(z0);
            __half h1 = __float2half_rn(z1);
            __half l0 = __float2half_rn(z0 - __half2float(h0));
            __half l1 = __float2half_rn(z1 - __half2float(h1));
            int d = zd + j;
            uint32_t off = rowA + (((d >> 3) ^ swm) << 4) + ((d & 7) * 2);
            *(uint32_t*)(aSt + off)         = packh(h0, h1);
            *(uint32_t*)(aSt + 16384 + off) = packh(l0, l1);
        }
    };

    computeA(0);

    float    acc [2][8][4];
    uint32_t hacc[2][8][2];
    #pragma unroll
    for (int a = 0; a < 2; a++)
        #pragma unroll
        for (int b = 0; b < 8; b++) {
            #pragma unroll
            for (int c = 0; c < 4; c++) acc[a][b][c] = 0.f;
            hacc[a][b][0] = 0u; hacc[a][b][1] = 0u;
        }

    for (int r = 0; r < 65; ++r) {
        asm volatile("cp.async.wait_group 0;");
        __syncthreads();                       // B[r] + A[r] visible; stage reuse safe
        if (r + 1 < 65) cpB((r + 1) & 1, r + 1);

        int s = r & 1;
        uint32_t aAhi = smem_u32(sA + s * 32768);
        uint32_t aAlo = aAhi + 16384;
        uint32_t aBhi = smem_u32(sB + s * 32768);
        uint32_t aBlo = aBhi + 16384;
        #pragma unroll
        for (int ks = 0; ks < 4; ++ks) {
            uint32_t ahi[2][4], alo[2][4];
            #pragma unroll
            for (int mt = 0; mt < 2; ++mt) {
                int rrow = wm*32 + mt*16 + (lane & 7) + ((lane >> 3) & 1) * 8;
                int g    = ks*2 + ((lane >> 4) & 1);
                uint32_t off = rrow*128 + ((g ^ (rrow & 7)) << 4);
                ldsm4(ahi[mt][0], ahi[mt][1], ahi[mt][2], ahi[mt][3], aAhi + off);
                ldsm4(alo[mt][0], alo[mt][1], alo[mt][2], alo[mt][3], aAlo + off);
            }
            #pragma unroll
            for (int p = 0; p < 4; ++p) {
                int krow = ks*16 + (lane & 7) + ((lane >> 3) & 1) * 8;
                int ncol = wn*64 + p*16 + ((lane >> 4) & 1) * 8;
                uint32_t off = krow*256 + ((((ncol >> 3) ^ (krow & 7))) << 4);
                uint32_t bhi[4], blo[4];
                ldsm4t(bhi[0], bhi[1], bhi[2], bhi[3], aBhi + off);
                ldsm4t(blo[0], blo[1], blo[2], blo[3], aBlo + off);
                #pragma unroll
                for (int mt = 0; mt < 2; ++mt) {
                    mma_f32(acc [mt][2*p],   ahi[mt], bhi);
                    mma_f16(hacc[mt][2*p],   alo[mt], bhi);
                    mma_f16(hacc[mt][2*p],   ahi[mt], blo);
                    mma_f32(acc [mt][2*p+1], ahi[mt], bhi + 2);
                    mma_f16(hacc[mt][2*p+1], alo[mt], bhi + 2);
                    mma_f16(hacc[mt][2*p+1], ahi[mt], blo + 2);
                }
            }
        }

        if (r + 1 < 65) computeA(r + 1);       // overlaps with tensor drain
    }

    // epilogue: combine f32 + f16 accumulators, write fp32 kv
    int gq = lane >> 2, t4 = lane & 3;
    #pragma unroll
    for (int mt = 0; mt < 2; ++mt) {
        #pragma unroll
        for (int ng = 0; ng < 8; ++ng) {
            __half2 q0 = *(__half2*)&hacc[mt][ng][0];
            __half2 q1 = *(__half2*)&hacc[mt][ng][1];
            float2 c01 = __half22float2(q0);
            float2 c23 = __half22float2(q1);
            int row = eb + wm*32 + mt*16 + gq;
            int col = ob + wn*64 + ng*8 + t4*2;
            *(float2*)&g_kv[(size_t)row*256 + col] =
                make_float2(acc[mt][ng][0] + c01.x, acc[mt][ng][1] + c01.y);
            *(float2*)&g_kv[(size_t)(row + 8)*256 + col] =
                make_float2(acc[mt][ng][2] + c23.x, acc[mt][ng][3] + c23.y);
        }
    }
}

// ------------------------------------------- attention + out-proj (fused)
__global__ void k_attout(const void* __restrict__ maskbuf,
                         const float* __restrict__ Wout,
                         float* __restrict__ out) {
    __shared__ float ao[HID];
    int node = blockIdx.x;
    int h = threadIdx.x >> 5, l = threadIdx.x & 31;
    float qv = g_q[node*128 + h*32 + l];
    int mode = g_maskmode;
    int ebase = node * 16;
    float sim[16];
    #pragma unroll
    for (int j = 0; j < 16; j++) {
        int e = ebase + j;
        float kvv = g_kv[(size_t)e*256 + h*32 + l];
        float df = qv - kvv + 1e-6f;
        float s = df * df;
        #pragma unroll
        for (int o = 16; o; o >>= 1) s += __shfl_xor_sync(0xffffffffu, s, o);
        bool m;
        if      (mode == 0) m = ((const unsigned char*)maskbuf)[e] != 0;
        else if (mode == 1) m = ((const int*)maskbuf)[e] != 0;
        else                m = ((const float*)maskbuf)[e] != 0.0f;
        sim[j] = m ? (-sqrtf(s) * 0.17677669529663687f)
                   : -3.4028234663852886e38f;
    }
    float mx = sim[0];
    #pragma unroll
    for (int j = 1; j < 16; j++) mx = fmaxf(mx, sim[j]);
    float w[16], Z = 0.f;
    #pragma unroll
    for (int j = 0; j < 16; j++) { w[j] = __expf(sim[j] - mx); Z += w[j]; }
    float inv = 1.0f / Z;
    float o = 0.f;
    #pragma unroll
    for (int j = 0; j < 16; j++)
        o = fmaf(w[j] * inv, g_kv[(size_t)(ebase+j)*256 + 128 + h*32 + l], o);
    ao[h*32 + l] = o;
    __syncthreads();
    int t = threadIdx.x;
    if (t < 64) {
        float acc = 0.f;
        #pragma unroll 16
        for (int i = 0; i < 128; i++) acc = fmaf(ao[i], Wout[i*64 + t], acc);
        out[node*64 + t] = acc;
    }
}

// -------------------------------------------------------------------- launch
extern "C" void kernel_launch(void* const* d_in, const int* in_sizes, int n_in,
                              void* d_out, int out_size) {
    const float* feat  = (const float*)d_in[0];
    const int*   nidx  = (const int*)  d_in[1];
    const void*  mask  =               d_in[2];
    const float* rel   = (const float*)d_in[3];
    const float* gamma = (const float*)d_in[4];
    const float* Wq    = (const float*)d_in[5];
    const float* Wxi   = (const float*)d_in[6];
    const float* Wxj   = (const float*)d_in[7];
    const float* W1    = (const float*)d_in[8];
    const float* b1    = (const float*)d_in[9];
    const float* g1    = (const float*)d_in[10];
    const float* W2    = (const float*)d_in[11];
    const float* b2    = (const float*)d_in[12];
    const float* g2    = (const float*)d_in[13];
    const float* W3    = (const float*)d_in[14];
    const float* b3    = (const float*)d_in[15];
    const float* Wkv   = (const float*)d_in[16];
    const float* Wout  = (const float*)d_in[17];

    cudaFuncSetAttribute(k_main, cudaFuncAttributeMaxDynamicSharedMemorySize,
                         SM_TOTAL_MAIN);

    k_prenorm_proj<<<BN + 1, 256>>>(feat, gamma, Wq, Wxi, Wxj,
                                    (const unsigned char*)mask);
    k_xe<<<NE*DD/256, 256>>>(nidx);
    k_fold_radial<<<260 + NE/8, 256>>>(W3, b3, Wkv, rel, W1, b1, g1, W2, b2, g2);
    k_main<<<dim3(64, 2), 256, SM_TOTAL_MAIN>>>();
    k_attout<<<BN, 128>>>(mask, Wout, (float*)d_out);
}